// round 3
// baseline (speedup 1.0000x reference)
#include <cuda_runtime.h>

// inputs: float32 [16, 64, 256, 256] NCHW
#define NB        16
#define NC        64
#define HW4       16384              // float4 per (n,c) slice
#define CHUNKS    64                 // reduce chunks over hw4
#define TPB       256
#define PERCHAN4  (NB * HW4)         // 262144 float4 per channel
#define TOTAL4    (NB * NC * HW4)    // 16,777,216 float4
#define EPS       1e-5f

// Deterministic partials: written unconditionally every call, no zeroing needed.
__device__ float g_psum[NC * CHUNKS];
__device__ float g_psq [NC * CHUNKS];

// grid = (NC, CHUNKS). Each thread: 16 fully-unrolled independent float4 loads.
__global__ void reduce_kernel(const float4* __restrict__ in) {
    const int c     = blockIdx.x;
    const int tglob = blockIdx.y * TPB + threadIdx.x;     // hw4 index
    const float4* p = in + (size_t)c * HW4 + tglob;

    float4 v[NB];
    #pragma unroll
    for (int n = 0; n < NB; n++)
        v[n] = __ldcg(&p[(size_t)n * NC * HW4]);

    float s = 0.0f, q = 0.0f;
    #pragma unroll
    for (int n = 0; n < NB; n++) {
        s += (v[n].x + v[n].y) + (v[n].z + v[n].w);
        q += (v[n].x * v[n].x + v[n].y * v[n].y)
           + (v[n].z * v[n].z + v[n].w * v[n].w);
    }

    #pragma unroll
    for (int off = 16; off > 0; off >>= 1) {
        s += __shfl_down_sync(0xffffffffu, s, off);
        q += __shfl_down_sync(0xffffffffu, q, off);
    }

    __shared__ float sh_s[8], sh_q[8];
    const int lane = threadIdx.x & 31;
    const int wid  = threadIdx.x >> 5;
    if (lane == 0) { sh_s[wid] = s; sh_q[wid] = q; }
    __syncthreads();

    if (wid == 0) {
        s = (lane < (TPB >> 5)) ? sh_s[lane] : 0.0f;
        q = (lane < (TPB >> 5)) ? sh_q[lane] : 0.0f;
        #pragma unroll
        for (int off = 4; off > 0; off >>= 1) {
            s += __shfl_down_sync(0xffffffffu, s, off);
            q += __shfl_down_sync(0xffffffffu, q, off);
        }
        if (lane == 0) {
            g_psum[c * CHUNKS + blockIdx.y] = s;
            g_psq [c * CHUNKS + blockIdx.y] = q;
        }
    }
}

// R1-style normalize (grid-stride, MLP=4, default caching) + inline per-block
// stats finalization from the 64 L2-resident partials (no separate kernel).
__global__ void normalize_kernel(const float4* __restrict__ in,
                                 float4* __restrict__ out) {
    __shared__ float sh_stats[2];   // mean, rstd

    const int nthreads = gridDim.x * blockDim.x;
    const int i0 = blockIdx.x * blockDim.x + threadIdx.x;
    // All 4 grid-stride positions of this block share one channel iff
    // nthreads is a multiple of HW4*NC? It isn't — c varies per k. So compute
    // per-k channel, but stats for *all* channels via smem table instead:
    __shared__ float sh_mean[NC], sh_rstd[NC];

    // First 64 threads each finalize one channel (64 seq adds from L2).
    if (threadIdx.x < NC) {
        const int c = threadIdx.x;
        float s = 0.0f, q = 0.0f;
        #pragma unroll
        for (int k = 0; k < CHUNKS; k++) {
            s += g_psum[c * CHUNKS + k];
            q += g_psq [c * CHUNKS + k];
        }
        const float invN = 1.0f / (float)(PERCHAN4 * 4);
        const float mean = s * invN;
        sh_mean[c] = mean;
        sh_rstd[c] = rsqrtf(q * invN - mean * mean + EPS);
    }
    __syncthreads();
    (void)sh_stats;

    int i = i0;
    #pragma unroll
    for (int k = 0; k < 4; k++, i += nthreads) {
        const int c = (i >> 14) & (NC - 1);
        const float mean = sh_mean[c];
        const float rstd = sh_rstd[c];
        float4 v = in[i];
        float4 o;
        o.x = (v.x - mean) * rstd;
        o.y = (v.y - mean) * rstd;
        o.z = (v.z - mean) * rstd;
        o.w = (v.w - mean) * rstd;
        out[i] = o;
    }
}

extern "C" void kernel_launch(void* const* d_in, const int* in_sizes, int n_in,
                              void* d_out, int out_size) {
    const float4* in  = (const float4*)d_in[0];
    float4*       out = (float4*)d_out;

    dim3 rgrid(NC, CHUNKS);
    reduce_kernel<<<rgrid, TPB>>>(in);
    normalize_kernel<<<TOTAL4 / (TPB * 4), TPB>>>(in, out);
}

// round 4
// speedup vs baseline: 4.1561x; 4.1561x over previous
#include <cuda_runtime.h>

// inputs: float32 [16, 64, 256, 256] NCHW
#define NB        16
#define NC        64
#define HW4       16384              // float4 per (n,c) slice
#define CHUNKS    64                 // reduce chunks over hw4
#define TPB       256
#define PERCHAN4  (NB * HW4)         // 262144 float4 per channel
#define TOTAL4    (NB * NC * HW4)    // 16,777,216 float4
#define EPS       1e-5f

// Deterministic partials: written unconditionally every call, no zeroing needed.
__device__ float g_psum[NC * CHUNKS];
__device__ float g_psq [NC * CHUNKS];
__device__ float g_scale[NC];   // rstd
__device__ float g_bias [NC];   // -mean * rstd

// grid = (NC, CHUNKS). Each thread: 16 fully-unrolled independent float4 loads.
__global__ void reduce_kernel(const float4* __restrict__ in) {
    const int c     = blockIdx.x;
    const int tglob = blockIdx.y * TPB + threadIdx.x;     // hw4 index
    const float4* p = in + (size_t)c * HW4 + tglob;

    float4 v[NB];
    #pragma unroll
    for (int n = 0; n < NB; n++)
        v[n] = __ldcg(&p[(size_t)n * NC * HW4]);

    float s = 0.0f, q = 0.0f;
    #pragma unroll
    for (int n = 0; n < NB; n++) {
        s += (v[n].x + v[n].y) + (v[n].z + v[n].w);
        q += (v[n].x * v[n].x + v[n].y * v[n].y)
           + (v[n].z * v[n].z + v[n].w * v[n].w);
    }

    #pragma unroll
    for (int off = 16; off > 0; off >>= 1) {
        s += __shfl_down_sync(0xffffffffu, s, off);
        q += __shfl_down_sync(0xffffffffu, q, off);
    }

    __shared__ float sh_s[8], sh_q[8];
    const int lane = threadIdx.x & 31;
    const int wid  = threadIdx.x >> 5;
    if (lane == 0) { sh_s[wid] = s; sh_q[wid] = q; }
    __syncthreads();

    if (wid == 0) {
        s = (lane < (TPB >> 5)) ? sh_s[lane] : 0.0f;
        q = (lane < (TPB >> 5)) ? sh_q[lane] : 0.0f;
        #pragma unroll
        for (int off = 4; off > 0; off >>= 1) {
            s += __shfl_down_sync(0xffffffffu, s, off);
            q += __shfl_down_sync(0xffffffffu, q, off);
        }
        if (lane == 0) {
            g_psum[c * CHUNKS + blockIdx.y] = s;
            g_psq [c * CHUNKS + blockIdx.y] = q;
        }
    }
}

// One 64-thread block folds partials and precomputes scale/bias per channel.
__global__ void finalize_kernel() {
    const int c = threadIdx.x;
    float s = 0.0f, q = 0.0f;
    #pragma unroll
    for (int k = 0; k < CHUNKS; k++) {
        s += g_psum[c * CHUNKS + k];
        q += g_psq [c * CHUNKS + k];
    }
    const float invN = 1.0f / (float)(PERCHAN4 * 4);
    const float mean = s * invN;
    const float rstd = rsqrtf(q * invN - mean * mean + EPS);
    g_scale[c] = rstd;
    g_bias[c]  = -mean * rstd;
}

// R1-proven normalize: grid-stride, 4 float4 per thread, default caching.
__global__ void normalize_kernel(const float4* __restrict__ in,
                                 float4* __restrict__ out) {
    const int nthreads = gridDim.x * blockDim.x;
    int i = blockIdx.x * blockDim.x + threadIdx.x;

    #pragma unroll
    for (int k = 0; k < 4; k++, i += nthreads) {
        const int c = (i >> 14) & (NC - 1);
        const float scale = g_scale[c];
        const float bias  = g_bias[c];
        float4 v = in[i];
        float4 o;
        o.x = fmaf(v.x, scale, bias);
        o.y = fmaf(v.y, scale, bias);
        o.z = fmaf(v.z, scale, bias);
        o.w = fmaf(v.w, scale, bias);
        out[i] = o;
    }
}

extern "C" void kernel_launch(void* const* d_in, const int* in_sizes, int n_in,
                              void* d_out, int out_size) {
    const float4* in  = (const float4*)d_in[0];
    float4*       out = (float4*)d_out;

    dim3 rgrid(NC, CHUNKS);
    reduce_kernel<<<rgrid, TPB>>>(in);
    finalize_kernel<<<1, NC>>>();
    normalize_kernel<<<TOTAL4 / (TPB * 4), TPB>>>(in, out);
}